// round 10
// baseline (speedup 1.0000x reference)
#include <cuda_runtime.h>
#include <math.h>

#define EPS_V    1e-6f
#define MARGIN_V 1.0f

// Scratch (allocation-free rule: __device__ globals)
__device__ float        g_partials[4096];
__device__ unsigned int g_count = 0;       // reset by last block each launch

// ---------------------------------------------------------------------------
// Fused kernel: d_ap (per-block, L2-hit) + streaming d_an + last-block reduce.
// 8 warps/block, one warp per negative row (grid-stride).
// ---------------------------------------------------------------------------
__global__ void __launch_bounds__(256) fused_kernel(
        const float* __restrict__ anchor,
        const float* __restrict__ pos,
        const float* __restrict__ neg,
        float* __restrict__ out,
        int D, int R, int P, int nBlocks) {
    extern __shared__ float4 s_a4[];       // D/4 float4 of anchor
    __shared__ float s_dap[8];             // P <= 8
    __shared__ float s_warp[8];
    __shared__ bool  s_last;
    __shared__ float s_red[32];

    const int D4   = D >> 2;
    const int lane = threadIdx.x & 31;
    const int wid  = threadIdx.x >> 5;

    // --- stage anchor into smem (vectorized) ---
    const float4* __restrict__ a4 = (const float4*)anchor;
    for (int i = threadIdx.x; i < D4; i += blockDim.x) s_a4[i] = a4[i];
    __syncthreads();

    // --- d_ap: warp p computes positive p (reads are L2 hits after 1st block) ---
    if (wid < P) {
        const float4* __restrict__ x4 = (const float4*)(pos + (size_t)wid * D);
        float ss = 0.0f;
        for (int i = lane; i < D4; i += 32) {
            float4 x = x4[i];
            float4 a = s_a4[i];
            float d0 = a.x - x.x + EPS_V;
            float d1 = a.y - x.y + EPS_V;
            float d2 = a.z - x.z + EPS_V;
            float d3 = a.w - x.w + EPS_V;
            ss = fmaf(d0, d0, ss);
            ss = fmaf(d1, d1, ss);
            ss = fmaf(d2, d2, ss);
            ss = fmaf(d3, d3, ss);
        }
        #pragma unroll
        for (int off = 16; off > 0; off >>= 1)
            ss += __shfl_xor_sync(0xffffffffu, ss, off);
        if (lane == 0) s_dap[wid] = sqrtf(ss);
    }
    __syncthreads();

    // --- streaming phase: one warp per negative row, grid-stride ---
    const int W  = nBlocks * 8;            // total warps
    const int gw = blockIdx.x * 8 + wid;   // global warp id
    float acc = 0.0f;                      // identical across lanes (butterfly)
    for (int row = gw; row < R; row += W) {
        const float4* __restrict__ x4 = (const float4*)(neg + (size_t)row * D);
        float ss = 0.0f;
        #pragma unroll 4
        for (int i = lane; i < D4; i += 32) {
            float4 x = x4[i];
            float4 a = s_a4[i];
            float d0 = a.x - x.x + EPS_V;
            float d1 = a.y - x.y + EPS_V;
            float d2 = a.z - x.z + EPS_V;
            float d3 = a.w - x.w + EPS_V;
            ss = fmaf(d0, d0, ss);
            ss = fmaf(d1, d1, ss);
            ss = fmaf(d2, d2, ss);
            ss = fmaf(d3, d3, ss);
        }
        #pragma unroll
        for (int off = 16; off > 0; off >>= 1)
            ss += __shfl_xor_sync(0xffffffffu, ss, off);
        float t = s_dap[row % P] - sqrtf(ss) + MARGIN_V;
        acc += fmaxf(t, 0.0f);
    }

    // --- block partial (fixed order: warp 0..7) ---
    if (lane == 0) s_warp[wid] = acc;
    __syncthreads();
    if (threadIdx.x == 0) {
        float tot = 0.0f;
        #pragma unroll
        for (int w = 0; w < 8; ++w) tot += s_warp[w];
        g_partials[blockIdx.x] = tot;
        __threadfence();
        unsigned int old = atomicAdd(&g_count, 1u);
        s_last = (old == (unsigned)(nBlocks - 1));
    }
    __syncthreads();

    // --- last block: deterministic final reduce + counter reset ---
    if (s_last) {
        __threadfence();
        float a2 = 0.0f;
        for (int i = threadIdx.x; i < nBlocks; i += blockDim.x)
            a2 += g_partials[i];
        #pragma unroll
        for (int off = 16; off > 0; off >>= 1)
            a2 += __shfl_xor_sync(0xffffffffu, a2, off);
        if (lane == 0) s_red[wid] = a2;
        __syncthreads();
        if (threadIdx.x == 0) {
            float tot = 0.0f;
            #pragma unroll
            for (int w = 0; w < 8; ++w) tot += s_red[w];
            out[0] = tot;
            g_count = 0;                  // reset for next graph replay
        }
    }
}

// ---------------------------------------------------------------------------
extern "C" void kernel_launch(void* const* d_in, const int* in_sizes, int n_in,
                              void* d_out, int out_size) {
    const float* anchor = (const float*)d_in[0];
    const float* pos    = (const float*)d_in[1];
    const float* neg    = (const float*)d_in[2];
    float* out          = (float*)d_out;

    const int D = in_sizes[0];            // 2400
    const int P = in_sizes[1] / D;        // 5
    const int N = in_sizes[2] / D;        // 50000
    const int C = N / P;                  // 10000
    const int R = C * P;                  // rows actually used

    const int nBlocks = 592;              // 4 blocks/SM on 148 SMs
    const size_t smem = (size_t)(D >> 2) * sizeof(float4);
    fused_kernel<<<nBlocks, 256, smem>>>(anchor, pos, neg, out, D, R, P, nBlocks);
}